// round 14
// baseline (speedup 1.0000x reference)
#include <cuda_runtime.h>
#include <cuda_fp16.h>
#include <math.h>
#include <stdint.h>

#define BB 8
#define TT 2048
#define CC 1024
#define HH 128

__device__ __align__(16) __half g_q[BB * TT * HH];
__device__ __align__(16) __half g_k[BB * TT * HH];
__device__ __align__(16) __half g_vt[BB * HH * TT];   // V transposed: [b][h][t]
__device__ __align__(16) __half g_xh[BB * TT * CC];   // x in fp16
__device__ __align__(16) __half g_wh[3 * HH * CC];    // Wq/Wk/Wv in fp16

// Split-KV partials for heavy q-tiles (qt 16..31): O unnormalized + m,l
__device__ __align__(16) float g_po[BB][16][2][64][HH];   // 16 MB
__device__ __align__(16) float g_pm[BB][16][2][64];
__device__ __align__(16) float g_pl[BB][16][2][64];

// ---------------------------------------------------------------------------
// PTX helpers
// ---------------------------------------------------------------------------
__device__ __forceinline__ void mma_f16(float c[4], const uint32_t a[4],
                                        uint32_t b0, uint32_t b1) {
    asm volatile(
        "mma.sync.aligned.m16n8k16.row.col.f32.f16.f16.f32 "
        "{%0,%1,%2,%3}, {%4,%5,%6,%7}, {%8,%9}, {%0,%1,%2,%3};"
        : "+f"(c[0]), "+f"(c[1]), "+f"(c[2]), "+f"(c[3])
        : "r"(a[0]), "r"(a[1]), "r"(a[2]), "r"(a[3]), "r"(b0), "r"(b1));
}

__device__ __forceinline__ void ldsm_x4(uint32_t r[4], uint32_t addr) {
    asm volatile("ldmatrix.sync.aligned.m8n8.x4.shared.b16 {%0,%1,%2,%3}, [%4];"
        : "=r"(r[0]), "=r"(r[1]), "=r"(r[2]), "=r"(r[3]) : "r"(addr));
}

__device__ __forceinline__ uint32_t smem_u32(const void* p) {
    uint32_t a;
    asm("{ .reg .u64 t; cvta.to.shared.u64 t, %1; cvt.u32.u64 %0, t; }" : "=r"(a) : "l"(p));
    return a;
}

#define CP_ASYNC16(dst, src) \
    asm volatile("cp.async.cg.shared.global [%0], [%1], 16;" :: "r"(dst), "l"(src) : "memory")
#define CP_COMMIT() asm volatile("cp.async.commit_group;" ::: "memory")
#define CP_WAIT0()  asm volatile("cp.async.wait_group 0;" ::: "memory")
#define CP_WAIT1()  asm volatile("cp.async.wait_group 1;" ::: "memory")
#define CP_WAIT2()  asm volatile("cp.async.wait_group 2;" ::: "memory")

__device__ __forceinline__ uint32_t h2u(float a, float b) {
    __half2 h = __floats2half2_rn(a, b);
    return *reinterpret_cast<uint32_t*>(&h);
}

// ===========================================================================
// Kernel 0: fp32 -> fp16 conversion (x and the three W matrices).
// ===========================================================================
__global__ __launch_bounds__(256) void conv_f2h(
    const float4* __restrict__ src, int which, int n8)
{
    int i = blockIdx.x * 256 + threadIdx.x;
    if (i >= n8) return;
    __half* dst = (which == 0) ? g_xh : g_wh + (size_t)(which - 1) * (HH * CC);
    float4 a = src[2 * i];
    float4 b = src[2 * i + 1];
    uint4 o = make_uint4(h2u(a.x, a.y), h2u(a.z, a.w),
                         h2u(b.x, b.y), h2u(b.z, b.w));
    reinterpret_cast<uint4*>(dst)[i] = o;
}

// ===========================================================================
// Kernel 1: QKV projection, pure fp16, cp.async 2-stage, BM=64, BK=64.
// out[r][h] = sum_c xh[r][c] * wh[h][c].  M=16384, N=128, K=1024.
// 256 threads = 8 warps (4 M-groups x 16 rows, 2 N-groups x 64 cols).
// Smem per stage: A 64x144B + B 128x144B = 27648B; x2 = 55296B -> occ 3.
// Grid (256, 3): fine-grained to kill wave quantization (768 CTAs / 444 slots).
// ===========================================================================
#define QKROW 144
#define QKB_OFF 9216             // B tile offset within stage (A: 64*144)
#define QKSTG 27648
#define QKV_SMEM_BYTES (2 * QKSTG)

__global__ __launch_bounds__(256, 3) void qkv_mma_kernel()
{
    extern __shared__ char smc[];
    const uint32_t sb = smem_u32(smc);
    const int mat = blockIdx.y;
    const __half* whm = g_wh + (size_t)mat * (HH * CC);

    const int tid = threadIdx.x;
    const int lid = tid & 31;
    const int wid = tid >> 5;
    const int g = lid >> 2;
    const int c = lid & 3;
    const int wm = wid & 3;       // M group (16 rows)
    const int wn = wid >> 2;      // N group (64 cols)
    const int m0 = blockIdx.x * 64;

    const uint32_t lrow = lid & 15;
    const uint32_t lhi  = lid >> 4;

    float acc[8][4];
    #pragma unroll
    for (int ni = 0; ni < 8; ni++)
        #pragma unroll
        for (int j = 0; j < 4; j++) acc[ni][j] = 0.0f;

    // stage loader: A 64 rows x 8 chunks (2/thread), B 128 rows x 8 (4/thread)
    auto cpa_stage = [&](int p, int kt) {
        const int k0 = kt * 64;
        const uint32_t base = sb + p * QKSTG;
        #pragma unroll
        for (int i = 0; i < 2; i++) {
            int idx = tid + i * 256;
            int r = idx >> 3, ch = idx & 7;
            CP_ASYNC16(base + r * QKROW + ch * 16,
                       g_xh + (size_t)(m0 + r) * CC + k0 + ch * 8);
        }
        #pragma unroll
        for (int i = 0; i < 4; i++) {
            int idx = tid + i * 256;
            int r = idx >> 3, ch = idx & 7;
            CP_ASYNC16(base + QKB_OFF + r * QKROW + ch * 16,
                       whm + (size_t)r * CC + k0 + ch * 8);
        }
    };

    cpa_stage(0, 0);
    CP_COMMIT();
    cpa_stage(1, 1);
    CP_COMMIT();
    CP_WAIT1();
    __syncthreads();

    for (int kt = 0; kt < 16; ++kt) {
        const int p = kt & 1;
        const uint32_t abase = sb + p * QKSTG;
        const uint32_t bbase = abase + QKB_OFF;

        #pragma unroll
        for (int ks = 0; ks < 4; ks++) {
            const uint32_t choff = (ks * 2 + lhi) * 16;
            uint32_t a0[4];
            ldsm_x4(a0, abase + (wm * 16 + lrow) * QKROW + choff);
            #pragma unroll
            for (int nt2 = 0; nt2 < 4; nt2++) {
                uint32_t b4[4];
                ldsm_x4(b4, bbase + (wn * 64 + nt2 * 16 + lrow) * QKROW + choff);
                mma_f16(acc[2 * nt2],     a0, b4[0], b4[2]);
                mma_f16(acc[2 * nt2 + 1], a0, b4[1], b4[3]);
            }
        }

        if (kt < 14) {
            __syncthreads();
            cpa_stage(p, kt + 2);
            CP_COMMIT();
            CP_WAIT1();
            __syncthreads();
        } else if (kt == 14) {
            CP_WAIT0();
            __syncthreads();
        }
    }

    if (mat < 2) {
        __half* out = (mat == 0) ? g_q : g_k;
        int row0 = m0 + wm * 16 + g;
        int row1 = row0 + 8;
        #pragma unroll
        for (int ni = 0; ni < 8; ni++) {
            int col = wn * 64 + ni * 8 + 2 * c;
            *reinterpret_cast<uint32_t*>(&out[(size_t)row0 * HH + col]) =
                h2u(acc[ni][0], acc[ni][1]);
            *reinterpret_cast<uint32_t*>(&out[(size_t)row1 * HH + col]) =
                h2u(acc[ni][2], acc[ni][3]);
        }
    } else {
        __half* vtb = g_vt + (size_t)(m0 / TT) * HH * TT;
        const int tbase = m0 % TT;
        int t0 = tbase + wm * 16 + g;
        int t1 = t0 + 8;
        #pragma unroll
        for (int ni = 0; ni < 8; ni++) {
            int col = wn * 64 + ni * 8 + 2 * c;
            vtb[(size_t)col * TT + t0]       = __float2half_rn(acc[ni][0]);
            vtb[(size_t)(col + 1) * TT + t0] = __float2half_rn(acc[ni][1]);
            vtb[(size_t)col * TT + t1]       = __float2half_rn(acc[ni][2]);
            vtb[(size_t)(col + 1) * TT + t1] = __float2half_rn(acc[ni][3]);
        }
    }
}

// ===========================================================================
// Kernel 2: causal flash attention phase 1, split-KV (R10, unchanged).
// ===========================================================================
#define QSTR  272
#define VSTR  144
#define AQb   0
#define AK0b  17408
#define AK1b  34816
#define AVT0b 52224
#define AVT1b 70656
#define APb   89088
#define ATT_SMEM_BYTES 98304

__global__ __launch_bounds__(128, 2) void attn_mma_kernel(float* __restrict__ out)
{
    extern __shared__ char smc[];
    const uint32_t sb = smem_u32(smc);

    const int b  = blockIdx.y;
    const int widx = 47 - blockIdx.x;          // heavy splits scheduled first
    int qt, ktlo, kthi, split = 0, qh = 0;
    bool partial;
    if (widx < 16) {
        qt = widx; ktlo = 0; kthi = qt; partial = false;
    } else {
        int h = widx - 16;
        qh = h >> 1;
        qt = 16 + qh;
        split = h & 1;
        int first = (qt + 2) >> 1;             // tiles in split 0
        ktlo = split ? first : 0;
        kthi = split ? qt : first - 1;
        partial = true;
    }
    const int q0 = qt * 64;

    const int tid = threadIdx.x;
    const int wid = tid >> 5;
    const int lid = tid & 31;
    const int g = lid >> 2;
    const int c = lid & 3;
    const int r0w = wid * 16;

    const __half* qg  = g_q  + (size_t)b * TT * HH;
    const __half* kg  = g_k  + (size_t)b * TT * HH;
    const __half* vtg = g_vt + (size_t)b * HH * TT;

    auto cpa64 = [&](uint32_t dstb, const __half* src) {
        #pragma unroll
        for (int i = 0; i < 8; i++) {
            int idx = tid + i * 128;
            int r = idx >> 4, ch = idx & 15;
            CP_ASYNC16(sb + dstb + r * QSTR + ch * 16,
                       src + (size_t)r * HH + ch * 8);
        }
    };
    auto cpa_vt = [&](uint32_t dstb, int kt) {
        const __half* src = vtg + kt * 64;
        #pragma unroll
        for (int i = 0; i < 8; i++) {
            int idx = tid + i * 128;
            int r = idx >> 3, ch = idx & 7;
            CP_ASYNC16(sb + dstb + r * VSTR + ch * 16,
                       src + (size_t)r * TT + ch * 8);
        }
    };

    // Prologue
    cpa64(AQb, qg + (size_t)q0 * HH);
    cpa64(AK0b, kg + (size_t)ktlo * 64 * HH);
    CP_COMMIT();
    cpa_vt(AVT0b, ktlo);
    CP_COMMIT();
    CP_WAIT1();
    __syncthreads();

    const uint32_t lrow = lid & 15;
    const uint32_t lhi  = lid >> 4;

    uint32_t qa[8][4];
    {
        const uint32_t qrb = sb + AQb + (r0w + lrow) * QSTR;
        #pragma unroll
        for (int ks = 0; ks < 8; ks++)
            ldsm_x4(qa[ks], qrb + (ks * 2 + lhi) * 16);
    }

    float o[16][4];
    #pragma unroll
    for (int nt = 0; nt < 16; nt++)
        #pragma unroll
        for (int j = 0; j < 4; j++) o[nt][j] = 0.0f;
    float m0s = -1e30f, m1s = -1e30f, l0 = 0.0f, l1 = 0.0f;

    const float sc2 = 0.08838834764831845f * 1.4426950408889634f;
    const int grow0 = q0 + r0w + g;
    const int grow1 = grow0 + 8;

    for (int kt = ktlo; kt <= kthi; ++kt) {
        const int p = (kt - ktlo) & 1;
        const uint32_t kbase  = sb + (p ? AK1b : AK0b);
        const uint32_t vtbase = sb + (p ? AVT1b : AVT0b);

        if (kt < kthi) {
            cpa64(p ? AK0b : AK1b, kg + (size_t)(kt + 1) * 64 * HH);
            CP_COMMIT();
            cpa_vt(p ? AVT0b : AVT1b, kt + 1);
            CP_COMMIT();
            CP_WAIT2();
        } else {
            CP_WAIT0();
        }
        __syncthreads();

        // ---- S = Q K^T ----
        float sa[8][4];
        #pragma unroll
        for (int nt = 0; nt < 8; nt++)
            #pragma unroll
            for (int j = 0; j < 4; j++) sa[nt][j] = 0.0f;

        #pragma unroll
        for (int ks = 0; ks < 8; ks++) {
            const uint32_t choff = (ks * 2 + lhi) * 16;
            #pragma unroll
            for (int nt2 = 0; nt2 < 4; nt2++) {
                uint32_t kb[4];
                ldsm_x4(kb, kbase + (nt2 * 16 + lrow) * QSTR + choff);
                mma_f16(sa[2 * nt2],     qa[ks], kb[0], kb[2]);
                mma_f16(sa[2 * nt2 + 1], qa[ks], kb[1], kb[3]);
            }
        }

        // scale (log2 units) + causal mask on the diagonal tile
        const int k0 = kt * 64;
        #pragma unroll
        for (int nt = 0; nt < 8; nt++)
            #pragma unroll
            for (int j = 0; j < 4; j++) sa[nt][j] *= sc2;
        if (kt == qt) {
            #pragma unroll
            for (int nt = 0; nt < 8; nt++) {
                int colb = k0 + nt * 8 + 2 * c;
                if (colb     > grow0) sa[nt][0] = -1e30f;
                if (colb + 1 > grow0) sa[nt][1] = -1e30f;
                if (colb     > grow1) sa[nt][2] = -1e30f;
                if (colb + 1 > grow1) sa[nt][3] = -1e30f;
            }
        }

        // online softmax (base-2)
        float mt0 = -1e30f, mt1 = -1e30f;
        #pragma unroll
        for (int nt = 0; nt < 8; nt++) {
            mt0 = fmaxf(mt0, fmaxf(sa[nt][0], sa[nt][1]));
            mt1 = fmaxf(mt1, fmaxf(sa[nt][2], sa[nt][3]));
        }
        mt0 = fmaxf(mt0, __shfl_xor_sync(0xffffffffu, mt0, 1));
        mt0 = fmaxf(mt0, __shfl_xor_sync(0xffffffffu, mt0, 2));
        mt1 = fmaxf(mt1, __shfl_xor_sync(0xffffffffu, mt1, 1));
        mt1 = fmaxf(mt1, __shfl_xor_sync(0xffffffffu, mt1, 2));

        const float mn0 = fmaxf(m0s, mt0);
        const float mn1 = fmaxf(m1s, mt1);
        const float al0 = exp2f(m0s - mn0);
        const float al1 = exp2f(m1s - mn1);
        m0s = mn0; m1s = mn1;

        float lt0 = 0.0f, lt1 = 0.0f;
        #pragma unroll
        for (int nt = 0; nt < 8; nt++) {
            sa[nt][0] = exp2f(sa[nt][0] - mn0);
            sa[nt][1] = exp2f(sa[nt][1] - mn0);
            sa[nt][2] = exp2f(sa[nt][2] - mn1);
            sa[nt][3] = exp2f(sa[nt][3] - mn1);
            lt0 += sa[nt][0] + sa[nt][1];
            lt1 += sa[nt][2] + sa[nt][3];
        }
        lt0 += __shfl_xor_sync(0xffffffffu, lt0, 1);
        lt0 += __shfl_xor_sync(0xffffffffu, lt0, 2);
        lt1 += __shfl_xor_sync(0xffffffffu, lt1, 1);
        lt1 += __shfl_xor_sync(0xffffffffu, lt1, 2);
        l0 = l0 * al0 + lt0;
        l1 = l1 * al1 + lt1;

        #pragma unroll
        for (int nt = 0; nt < 16; nt++) {
            o[nt][0] *= al0; o[nt][1] *= al0;
            o[nt][2] *= al1; o[nt][3] *= al1;
        }

        // P -> smem fp16 (warp-private rows, padded 144B rows)
        {
            char* pr0 = smc + APb + (r0w + g) * VSTR + c * 4;
            char* pr8 = pr0 + 8 * VSTR;
            #pragma unroll
            for (int nt = 0; nt < 8; nt++) {
                *reinterpret_cast<uint32_t*>(pr0 + nt * 16) = h2u(sa[nt][0], sa[nt][1]);
                *reinterpret_cast<uint32_t*>(pr8 + nt * 16) = h2u(sa[nt][2], sa[nt][3]);
            }
        }
        __syncwarp();

        // ---- O += P V ----
        #pragma unroll
        for (int ks2 = 0; ks2 < 4; ks2++) {
            const uint32_t choff = (ks2 * 2 + lhi) * 16;
            uint32_t pa[4];
            ldsm_x4(pa, sb + APb + (r0w + lrow) * VSTR + choff);
            #pragma unroll
            for (int ntv = 0; ntv < 8; ntv++) {
                uint32_t vb[4];
                ldsm_x4(vb, vtbase + (ntv * 16 + lrow) * VSTR + choff);
                mma_f16(o[2 * ntv],     pa, vb[0], vb[2]);
                mma_f16(o[2 * ntv + 1], pa, vb[1], vb[3]);
            }
        }
        __syncthreads();
    }

    const int lr0 = r0w + g;
    const int lr1 = lr0 + 8;

    if (!partial) {
        const float inv0 = 1.0f / l0;
        const float inv1 = 1.0f / l1;
        #pragma unroll
        for (int nt = 0; nt < 16; nt++) {
            int col = nt * 8 + 2 * c;
            float2 v0 = make_float2(o[nt][0] * inv0, o[nt][1] * inv0);
            float2 v1 = make_float2(o[nt][2] * inv1, o[nt][3] * inv1);
            *reinterpret_cast<float2*>(&out[((size_t)b * TT + grow0) * HH + col]) = v0;
            *reinterpret_cast<float2*>(&out[((size_t)b * TT + grow1) * HH + col]) = v1;
        }
    } else {
        if (c == 0) {
            g_pm[b][qh][split][lr0] = m0s;
            g_pl[b][qh][split][lr0] = l0;
            g_pm[b][qh][split][lr1] = m1s;
            g_pl[b][qh][split][lr1] = l1;
        }
        #pragma unroll
        for (int nt = 0; nt < 16; nt++) {
            int col = nt * 8 + 2 * c;
            *reinterpret_cast<float2*>(&g_po[b][qh][split][lr0][col]) =
                make_float2(o[nt][0], o[nt][1]);
            *reinterpret_cast<float2*>(&g_po[b][qh][split][lr1][col]) =
                make_float2(o[nt][2], o[nt][3]);
        }
    }
}

// ===========================================================================
// Kernel 3: combine split-KV partials for heavy q-tiles.  grid (16, 8).
// ===========================================================================
__global__ __launch_bounds__(256) void attn_combine(float* __restrict__ out)
{
    const int b = blockIdx.y;
    const int qh = blockIdx.x;
    const int qt = 16 + qh;
    const int t = threadIdx.x;
    const int colb = (t & 31) * 4;
    const int rbase = t >> 5;

    #pragma unroll
    for (int pass = 0; pass < 8; pass++) {
        const int row = pass * 8 + rbase;
        const float m0 = g_pm[b][qh][0][row];
        const float m1 = g_pm[b][qh][1][row];
        const float m = fmaxf(m0, m1);
        const float a0 = exp2f(m0 - m);
        const float a1 = exp2f(m1 - m);
        const float invl = 1.0f / (g_pl[b][qh][0][row] * a0 + g_pl[b][qh][1][row] * a1);
        const float4 O0 = *reinterpret_cast<const float4*>(&g_po[b][qh][0][row][colb]);
        const float4 O1 = *reinterpret_cast<const float4*>(&g_po[b][qh][1][row][colb]);
        float4 r;
        r.x = (O0.x * a0 + O1.x * a1) * invl;
        r.y = (O0.y * a0 + O1.y * a1) * invl;
        r.z = (O0.z * a0 + O1.z * a1) * invl;
        r.w = (O0.w * a0 + O1.w * a1) * invl;
        *reinterpret_cast<float4*>(
            &out[((size_t)b * TT + qt * 64 + row) * HH + colb]) = r;
    }
}

// ---------------------------------------------------------------------------
extern "C" void kernel_launch(void* const* d_in, const int* in_sizes, int n_in,
                              void* d_out, int out_size)
{
    const float* x  = (const float*)d_in[0];
    const float* Wq = (const float*)d_in[1];
    const float* Wk = (const float*)d_in[2];
    const float* Wv = (const float*)d_in[3];
    float* out = (float*)d_out;

    cudaFuncSetAttribute(qkv_mma_kernel, cudaFuncAttributeMaxDynamicSharedMemorySize,
                         QKV_SMEM_BYTES);
    cudaFuncSetAttribute(attn_mma_kernel, cudaFuncAttributeMaxDynamicSharedMemorySize,
                         ATT_SMEM_BYTES);

    conv_f2h<<<(BB * TT * CC / 8 + 255) / 256, 256>>>((const float4*)x, 0, BB * TT * CC / 8);
    conv_f2h<<<(HH * CC / 8 + 255) / 256, 256>>>((const float4*)Wq, 1, HH * CC / 8);
    conv_f2h<<<(HH * CC / 8 + 255) / 256, 256>>>((const float4*)Wk, 2, HH * CC / 8);
    conv_f2h<<<(HH * CC / 8 + 255) / 256, 256>>>((const float4*)Wv, 3, HH * CC / 8);

    dim3 g1((BB * TT) / 64, 3);
    qkv_mma_kernel<<<g1, 256, QKV_SMEM_BYTES>>>();

    dim3 g2(48, BB);
    attn_mma_kernel<<<g2, 128, ATT_SMEM_BYTES>>>(out);

    dim3 g3(16, BB);
    attn_combine<<<g3, 256>>>(out);
}

// round 15
// speedup vs baseline: 1.0406x; 1.0406x over previous
#include <cuda_runtime.h>
#include <cuda_fp16.h>
#include <math.h>
#include <stdint.h>

#define BB 8
#define TT 2048
#define CC 1024
#define HH 128

__device__ __align__(16) __half g_q[BB * TT * HH];
__device__ __align__(16) __half g_k[BB * TT * HH];
__device__ __align__(16) __half g_vt[BB * HH * TT];   // V transposed: [b][h][t]
__device__ __align__(16) __half g_xh[BB * TT * CC];   // x in fp16
__device__ __align__(16) __half g_wh[3 * HH * CC];    // Wq/Wk/Wv in fp16

// Split-KV partials for heavy q-tiles (qt 16..31): O unnormalized + m,l
__device__ __align__(16) float g_po[BB][16][2][64][HH];   // 16 MB
__device__ __align__(16) float g_pm[BB][16][2][64];
__device__ __align__(16) float g_pl[BB][16][2][64];

// ---------------------------------------------------------------------------
// PTX helpers
// ---------------------------------------------------------------------------
__device__ __forceinline__ void mma_f16(float c[4], const uint32_t a[4],
                                        uint32_t b0, uint32_t b1) {
    asm volatile(
        "mma.sync.aligned.m16n8k16.row.col.f32.f16.f16.f32 "
        "{%0,%1,%2,%3}, {%4,%5,%6,%7}, {%8,%9}, {%0,%1,%2,%3};"
        : "+f"(c[0]), "+f"(c[1]), "+f"(c[2]), "+f"(c[3])
        : "r"(a[0]), "r"(a[1]), "r"(a[2]), "r"(a[3]), "r"(b0), "r"(b1));
}

__device__ __forceinline__ void ldsm_x4(uint32_t r[4], uint32_t addr) {
    asm volatile("ldmatrix.sync.aligned.m8n8.x4.shared.b16 {%0,%1,%2,%3}, [%4];"
        : "=r"(r[0]), "=r"(r[1]), "=r"(r[2]), "=r"(r[3]) : "r"(addr));
}

__device__ __forceinline__ uint32_t smem_u32(const void* p) {
    uint32_t a;
    asm("{ .reg .u64 t; cvta.to.shared.u64 t, %1; cvt.u32.u64 %0, t; }" : "=r"(a) : "l"(p));
    return a;
}

#define CP_ASYNC16(dst, src) \
    asm volatile("cp.async.cg.shared.global [%0], [%1], 16;" :: "r"(dst), "l"(src) : "memory")
#define CP_COMMIT() asm volatile("cp.async.commit_group;" ::: "memory")
#define CP_WAIT0()  asm volatile("cp.async.wait_group 0;" ::: "memory")
#define CP_WAIT1()  asm volatile("cp.async.wait_group 1;" ::: "memory")

__device__ __forceinline__ uint32_t h2u(float a, float b) {
    __half2 h = __floats2half2_rn(a, b);
    return *reinterpret_cast<uint32_t*>(&h);
}

// ===========================================================================
// Kernel 0: fp32 -> fp16 conversion (x and the three W matrices).
// ===========================================================================
__global__ __launch_bounds__(256) void conv_f2h(
    const float4* __restrict__ src, int which, int n8)
{
    int i = blockIdx.x * 256 + threadIdx.x;
    if (i >= n8) return;
    __half* dst = (which == 0) ? g_xh : g_wh + (size_t)(which - 1) * (HH * CC);
    float4 a = src[2 * i];
    float4 b = src[2 * i + 1];
    uint4 o = make_uint4(h2u(a.x, a.y), h2u(a.z, a.w),
                         h2u(b.x, b.y), h2u(b.z, b.w));
    reinterpret_cast<uint4*>(dst)[i] = o;
}

// ===========================================================================
// Kernel 1: QKV projection — R10 version (BM=128, BK=64, occ 2).  REVERTED.
// ===========================================================================
#define QKROW 144
#define QKB_OFF 18432
#define QKSTG 36864
#define QKV_SMEM_BYTES (2 * QKSTG)

__global__ __launch_bounds__(256, 2) void qkv_mma_kernel()
{
    extern __shared__ char smc[];
    const uint32_t sb = smem_u32(smc);
    const int mat = blockIdx.y;
    const __half* whm = g_wh + (size_t)mat * (HH * CC);

    const int tid = threadIdx.x;
    const int lid = tid & 31;
    const int wid = tid >> 5;
    const int g = lid >> 2;
    const int c = lid & 3;
    const int wm = wid & 3;
    const int wn = wid >> 2;
    const int m0 = blockIdx.x * 128;

    const uint32_t lrow = lid & 15;
    const uint32_t lhi  = lid >> 4;

    float acc[2][8][4];
    #pragma unroll
    for (int mi = 0; mi < 2; mi++)
        #pragma unroll
        for (int ni = 0; ni < 8; ni++)
            #pragma unroll
            for (int j = 0; j < 4; j++) acc[mi][ni][j] = 0.0f;

    auto cpa_stage = [&](int p, int kt) {
        const int k0 = kt * 64;
        const uint32_t base = sb + p * QKSTG;
        #pragma unroll
        for (int i = 0; i < 4; i++) {
            int idx = tid + i * 256;
            int r = idx >> 3, ch = idx & 7;
            CP_ASYNC16(base + r * QKROW + ch * 16,
                       g_xh + (size_t)(m0 + r) * CC + k0 + ch * 8);
            CP_ASYNC16(base + QKB_OFF + r * QKROW + ch * 16,
                       whm + (size_t)r * CC + k0 + ch * 8);
        }
    };

    cpa_stage(0, 0);
    CP_COMMIT();
    cpa_stage(1, 1);
    CP_COMMIT();
    CP_WAIT1();
    __syncthreads();

    for (int kt = 0; kt < 16; ++kt) {
        const int p = kt & 1;
        const uint32_t abase = sb + p * QKSTG;
        const uint32_t bbase = abase + QKB_OFF;

        #pragma unroll
        for (int ks = 0; ks < 4; ks++) {
            const uint32_t choff = (ks * 2 + lhi) * 16;
            uint32_t a0[4], a1[4];
            ldsm_x4(a0, abase + (wm * 32 + lrow) * QKROW + choff);
            ldsm_x4(a1, abase + (wm * 32 + 16 + lrow) * QKROW + choff);
            #pragma unroll
            for (int nt2 = 0; nt2 < 4; nt2++) {
                uint32_t b4[4];
                ldsm_x4(b4, bbase + (wn * 64 + nt2 * 16 + lrow) * QKROW + choff);
                mma_f16(acc[0][2 * nt2],     a0, b4[0], b4[2]);
                mma_f16(acc[0][2 * nt2 + 1], a0, b4[1], b4[3]);
                mma_f16(acc[1][2 * nt2],     a1, b4[0], b4[2]);
                mma_f16(acc[1][2 * nt2 + 1], a1, b4[1], b4[3]);
            }
        }

        if (kt < 14) {
            __syncthreads();
            cpa_stage(p, kt + 2);
            CP_COMMIT();
            CP_WAIT1();
            __syncthreads();
        } else if (kt == 14) {
            CP_WAIT0();
            __syncthreads();
        }
    }

    if (mat < 2) {
        __half* out = (mat == 0) ? g_q : g_k;
        #pragma unroll
        for (int mi = 0; mi < 2; mi++) {
            int row0 = m0 + wm * 32 + mi * 16 + g;
            int row1 = row0 + 8;
            #pragma unroll
            for (int ni = 0; ni < 8; ni++) {
                int col = wn * 64 + ni * 8 + 2 * c;
                *reinterpret_cast<uint32_t*>(&out[(size_t)row0 * HH + col]) =
                    h2u(acc[mi][ni][0], acc[mi][ni][1]);
                *reinterpret_cast<uint32_t*>(&out[(size_t)row1 * HH + col]) =
                    h2u(acc[mi][ni][2], acc[mi][ni][3]);
            }
        }
    } else {
        __half* vtb = g_vt + (size_t)(m0 / TT) * HH * TT;
        const int tbase = m0 % TT;
        #pragma unroll
        for (int mi = 0; mi < 2; mi++) {
            int t0 = tbase + wm * 32 + mi * 16 + g;
            int t1 = t0 + 8;
            #pragma unroll
            for (int ni = 0; ni < 8; ni++) {
                int col = wn * 64 + ni * 8 + 2 * c;
                vtb[(size_t)col * TT + t0]       = __float2half_rn(acc[mi][ni][0]);
                vtb[(size_t)(col + 1) * TT + t0] = __float2half_rn(acc[mi][ni][1]);
                vtb[(size_t)col * TT + t1]       = __float2half_rn(acc[mi][ni][2]);
                vtb[(size_t)(col + 1) * TT + t1] = __float2half_rn(acc[mi][ni][3]);
            }
        }
    }
}

// ===========================================================================
// Kernel 2: causal flash attention phase 1, split-KV, SINGLE-buffered K/VT.
// Smem: Q 17408 + K 17408 + VT 18432 + P 9216 = 62464 B -> occ 3 (regs<=170).
// Prefetch overlap: K[kt+1] issued after S-loop (covered by softmax+PV),
// VT[kt+1] issued after PV (covered by next S-loop+softmax).
// ===========================================================================
#define QSTR  272
#define VSTR  144
#define AQb   0
#define AKb   17408
#define AVTb  34816
#define APb   53248
#define ATT_SMEM_BYTES 62464

__global__ __launch_bounds__(128, 3) void attn_mma_kernel(float* __restrict__ out)
{
    extern __shared__ char smc[];
    const uint32_t sb = smem_u32(smc);

    const int b  = blockIdx.y;
    const int widx = 47 - blockIdx.x;          // heavy splits scheduled first
    int qt, ktlo, kthi, split = 0, qh = 0;
    bool partial;
    if (widx < 16) {
        qt = widx; ktlo = 0; kthi = qt; partial = false;
    } else {
        int h = widx - 16;
        qh = h >> 1;
        qt = 16 + qh;
        split = h & 1;
        int first = (qt + 2) >> 1;             // tiles in split 0
        ktlo = split ? first : 0;
        kthi = split ? qt : first - 1;
        partial = true;
    }
    const int q0 = qt * 64;

    const int tid = threadIdx.x;
    const int wid = tid >> 5;
    const int lid = tid & 31;
    const int g = lid >> 2;
    const int c = lid & 3;
    const int r0w = wid * 16;

    const __half* qg  = g_q  + (size_t)b * TT * HH;
    const __half* kg  = g_k  + (size_t)b * TT * HH;
    const __half* vtg = g_vt + (size_t)b * HH * TT;

    auto cpa64 = [&](uint32_t dstb, const __half* src) {
        #pragma unroll
        for (int i = 0; i < 8; i++) {
            int idx = tid + i * 128;
            int r = idx >> 4, ch = idx & 15;
            CP_ASYNC16(sb + dstb + r * QSTR + ch * 16,
                       src + (size_t)r * HH + ch * 8);
        }
    };
    auto cpa_vt = [&](int kt) {
        const __half* src = vtg + kt * 64;
        #pragma unroll
        for (int i = 0; i < 8; i++) {
            int idx = tid + i * 128;
            int r = idx >> 3, ch = idx & 7;
            CP_ASYNC16(sb + AVTb + r * VSTR + ch * 16,
                       src + (size_t)r * TT + ch * 8);
        }
    };

    // Prologue: group1 = Q + K[ktlo], group2 = VT[ktlo]
    cpa64(AQb, qg + (size_t)q0 * HH);
    cpa64(AKb, kg + (size_t)ktlo * 64 * HH);
    CP_COMMIT();
    cpa_vt(ktlo);
    CP_COMMIT();
    CP_WAIT1();                        // Q + K[ktlo] ready (VT pending)
    __syncthreads();

    const uint32_t lrow = lid & 15;
    const uint32_t lhi  = lid >> 4;

    uint32_t qa[8][4];
    {
        const uint32_t qrb = sb + AQb + (r0w + lrow) * QSTR;
        #pragma unroll
        for (int ks = 0; ks < 8; ks++)
            ldsm_x4(qa[ks], qrb + (ks * 2 + lhi) * 16);
    }

    float o[16][4];
    #pragma unroll
    for (int nt = 0; nt < 16; nt++)
        #pragma unroll
        for (int j = 0; j < 4; j++) o[nt][j] = 0.0f;
    float m0s = -1e30f, m1s = -1e30f, l0 = 0.0f, l1 = 0.0f;

    const float sc2 = 0.08838834764831845f * 1.4426950408889634f;
    const int grow0 = q0 + r0w + g;
    const int grow1 = grow0 + 8;

    for (int kt = ktlo; kt <= kthi; ++kt) {
        if (kt > ktlo) {
            CP_WAIT1();                // K[kt] ready (VT[kt] pending)
            __syncthreads();
        }

        // ---- S = Q K^T ----
        float sa[8][4];
        #pragma unroll
        for (int nt = 0; nt < 8; nt++)
            #pragma unroll
            for (int j = 0; j < 4; j++) sa[nt][j] = 0.0f;

        #pragma unroll
        for (int ks = 0; ks < 8; ks++) {
            const uint32_t choff = (ks * 2 + lhi) * 16;
            #pragma unroll
            for (int nt2 = 0; nt2 < 4; nt2++) {
                uint32_t kb[4];
                ldsm_x4(kb, sb + AKb + (nt2 * 16 + lrow) * QSTR + choff);
                mma_f16(sa[2 * nt2],     qa[ks], kb[0], kb[2]);
                mma_f16(sa[2 * nt2 + 1], qa[ks], kb[1], kb[3]);
            }
        }

        __syncthreads();               // all warps done reading K[kt]
        if (kt < kthi) {               // K[kt+1] load overlaps softmax + PV
            cpa64(AKb, kg + (size_t)(kt + 1) * 64 * HH);
            CP_COMMIT();
        }

        // scale (log2 units) + causal mask on the diagonal tile
        const int k0 = kt * 64;
        #pragma unroll
        for (int nt = 0; nt < 8; nt++)
            #pragma unroll
            for (int j = 0; j < 4; j++) sa[nt][j] *= sc2;
        if (kt == qt) {
            #pragma unroll
            for (int nt = 0; nt < 8; nt++) {
                int colb = k0 + nt * 8 + 2 * c;
                if (colb     > grow0) sa[nt][0] = -1e30f;
                if (colb + 1 > grow0) sa[nt][1] = -1e30f;
                if (colb     > grow1) sa[nt][2] = -1e30f;
                if (colb + 1 > grow1) sa[nt][3] = -1e30f;
            }
        }

        // online softmax (base-2)
        float mt0 = -1e30f, mt1 = -1e30f;
        #pragma unroll
        for (int nt = 0; nt < 8; nt++) {
            mt0 = fmaxf(mt0, fmaxf(sa[nt][0], sa[nt][1]));
            mt1 = fmaxf(mt1, fmaxf(sa[nt][2], sa[nt][3]));
        }
        mt0 = fmaxf(mt0, __shfl_xor_sync(0xffffffffu, mt0, 1));
        mt0 = fmaxf(mt0, __shfl_xor_sync(0xffffffffu, mt0, 2));
        mt1 = fmaxf(mt1, __shfl_xor_sync(0xffffffffu, mt1, 1));
        mt1 = fmaxf(mt1, __shfl_xor_sync(0xffffffffu, mt1, 2));

        const float mn0 = fmaxf(m0s, mt0);
        const float mn1 = fmaxf(m1s, mt1);
        const float al0 = exp2f(m0s - mn0);
        const float al1 = exp2f(m1s - mn1);
        m0s = mn0; m1s = mn1;

        float lt0 = 0.0f, lt1 = 0.0f;
        #pragma unroll
        for (int nt = 0; nt < 8; nt++) {
            sa[nt][0] = exp2f(sa[nt][0] - mn0);
            sa[nt][1] = exp2f(sa[nt][1] - mn0);
            sa[nt][2] = exp2f(sa[nt][2] - mn1);
            sa[nt][3] = exp2f(sa[nt][3] - mn1);
            lt0 += sa[nt][0] + sa[nt][1];
            lt1 += sa[nt][2] + sa[nt][3];
        }
        lt0 += __shfl_xor_sync(0xffffffffu, lt0, 1);
        lt0 += __shfl_xor_sync(0xffffffffu, lt0, 2);
        lt1 += __shfl_xor_sync(0xffffffffu, lt1, 1);
        lt1 += __shfl_xor_sync(0xffffffffu, lt1, 2);
        l0 = l0 * al0 + lt0;
        l1 = l1 * al1 + lt1;

        #pragma unroll
        for (int nt = 0; nt < 16; nt++) {
            o[nt][0] *= al0; o[nt][1] *= al0;
            o[nt][2] *= al1; o[nt][3] *= al1;
        }

        // VT[kt] ready?  pending: {VT[kt], K[kt+1]} -> WAIT1; last iter: WAIT0
        if (kt < kthi) CP_WAIT1(); else CP_WAIT0();
        __syncthreads();

        // P -> smem fp16 (warp-private rows, padded 144B rows)
        {
            char* pr0 = smc + APb + (r0w + g) * VSTR + c * 4;
            char* pr8 = pr0 + 8 * VSTR;
            #pragma unroll
            for (int nt = 0; nt < 8; nt++) {
                *reinterpret_cast<uint32_t*>(pr0 + nt * 16) = h2u(sa[nt][0], sa[nt][1]);
                *reinterpret_cast<uint32_t*>(pr8 + nt * 16) = h2u(sa[nt][2], sa[nt][3]);
            }
        }
        __syncwarp();

        // ---- O += P V ----
        #pragma unroll
        for (int ks2 = 0; ks2 < 4; ks2++) {
            const uint32_t choff = (ks2 * 2 + lhi) * 16;
            uint32_t pa[4];
            ldsm_x4(pa, sb + APb + (r0w + lrow) * VSTR + choff);
            #pragma unroll
            for (int ntv = 0; ntv < 8; ntv++) {
                uint32_t vb[4];
                ldsm_x4(vb, sb + AVTb + (ntv * 16 + lrow) * VSTR + choff);
                mma_f16(o[2 * ntv],     pa, vb[0], vb[2]);
                mma_f16(o[2 * ntv + 1], pa, vb[1], vb[3]);
            }
        }
        __syncthreads();               // all warps done reading VT[kt]

        if (kt < kthi) {               // VT[kt+1] load overlaps next S + softmax
            cpa_vt(kt + 1);
            CP_COMMIT();
        }
    }

    const int lr0 = r0w + g;
    const int lr1 = lr0 + 8;

    if (!partial) {
        const float inv0 = 1.0f / l0;
        const float inv1 = 1.0f / l1;
        #pragma unroll
        for (int nt = 0; nt < 16; nt++) {
            int col = nt * 8 + 2 * c;
            float2 v0 = make_float2(o[nt][0] * inv0, o[nt][1] * inv0);
            float2 v1 = make_float2(o[nt][2] * inv1, o[nt][3] * inv1);
            *reinterpret_cast<float2*>(&out[((size_t)b * TT + grow0) * HH + col]) = v0;
            *reinterpret_cast<float2*>(&out[((size_t)b * TT + grow1) * HH + col]) = v1;
        }
    } else {
        if (c == 0) {
            g_pm[b][qh][split][lr0] = m0s;
            g_pl[b][qh][split][lr0] = l0;
            g_pm[b][qh][split][lr1] = m1s;
            g_pl[b][qh][split][lr1] = l1;
        }
        #pragma unroll
        for (int nt = 0; nt < 16; nt++) {
            int col = nt * 8 + 2 * c;
            *reinterpret_cast<float2*>(&g_po[b][qh][split][lr0][col]) =
                make_float2(o[nt][0], o[nt][1]);
            *reinterpret_cast<float2*>(&g_po[b][qh][split][lr1][col]) =
                make_float2(o[nt][2], o[nt][3]);
        }
    }
}

// ===========================================================================
// Kernel 3: combine split-KV partials for heavy q-tiles.  grid (16, 8).
// ===========================================================================
__global__ __launch_bounds__(256) void attn_combine(float* __restrict__ out)
{
    const int b = blockIdx.y;
    const int qh = blockIdx.x;
    const int qt = 16 + qh;
    const int t = threadIdx.x;
    const int colb = (t & 31) * 4;
    const int rbase = t >> 5;

    #pragma unroll
    for (int pass = 0; pass < 8; pass++) {
        const int row = pass * 8 + rbase;
        const float m0 = g_pm[b][qh][0][row];
        const float m1 = g_pm[b][qh][1][row];
        const float m = fmaxf(m0, m1);
        const float a0 = exp2f(m0 - m);
        const float a1 = exp2f(m1 - m);
        const float invl = 1.0f / (g_pl[b][qh][0][row] * a0 + g_pl[b][qh][1][row] * a1);
        const float4 O0 = *reinterpret_cast<const float4*>(&g_po[b][qh][0][row][colb]);
        const float4 O1 = *reinterpret_cast<const float4*>(&g_po[b][qh][1][row][colb]);
        float4 r;
        r.x = (O0.x * a0 + O1.x * a1) * invl;
        r.y = (O0.y * a0 + O1.y * a1) * invl;
        r.z = (O0.z * a0 + O1.z * a1) * invl;
        r.w = (O0.w * a0 + O1.w * a1) * invl;
        *reinterpret_cast<float4*>(
            &out[((size_t)b * TT + qt * 64 + row) * HH + colb]) = r;
    }
}

// ---------------------------------------------------------------------------
extern "C" void kernel_launch(void* const* d_in, const int* in_sizes, int n_in,
                              void* d_out, int out_size)
{
    const float* x  = (const float*)d_in[0];
    const float* Wq = (const float*)d_in[1];
    const float* Wk = (const float*)d_in[2];
    const float* Wv = (const float*)d_in[3];
    float* out = (float*)d_out;

    cudaFuncSetAttribute(qkv_mma_kernel, cudaFuncAttributeMaxDynamicSharedMemorySize,
                         QKV_SMEM_BYTES);
    cudaFuncSetAttribute(attn_mma_kernel, cudaFuncAttributeMaxDynamicSharedMemorySize,
                         ATT_SMEM_BYTES);

    conv_f2h<<<(BB * TT * CC / 8 + 255) / 256, 256>>>((const float4*)x, 0, BB * TT * CC / 8);
    conv_f2h<<<(HH * CC / 8 + 255) / 256, 256>>>((const float4*)Wq, 1, HH * CC / 8);
    conv_f2h<<<(HH * CC / 8 + 255) / 256, 256>>>((const float4*)Wk, 2, HH * CC / 8);
    conv_f2h<<<(HH * CC / 8 + 255) / 256, 256>>>((const float4*)Wv, 3, HH * CC / 8);

    dim3 g1((BB * TT) / 128, 3);
    qkv_mma_kernel<<<g1, 256, QKV_SMEM_BYTES>>>();

    dim3 g2(48, BB);
    attn_mma_kernel<<<g2, 128, ATT_SMEM_BYTES>>>(out);

    dim3 g3(16, BB);
    attn_combine<<<g3, 256>>>(out);
}

// round 16
// speedup vs baseline: 1.1122x; 1.0687x over previous
#include <cuda_runtime.h>
#include <cuda_fp16.h>
#include <math.h>
#include <stdint.h>

#define BB 8
#define TT 2048
#define CC 1024
#define HH 128

__device__ __align__(16) __half g_q[BB * TT * HH];    // pre-scaled by sc*log2e
__device__ __align__(16) __half g_k[BB * TT * HH];
__device__ __align__(16) __half g_vt[BB * HH * TT];   // V transposed: [b][h][t]
__device__ __align__(16) __half g_xh[BB * TT * CC];   // x in fp16
__device__ __align__(16) __half g_wh[3 * HH * CC];    // Wq/Wk/Wv in fp16

// Split-KV partials for heavy q-tiles (qt 16..31): O unnormalized + m,l
__device__ __align__(16) float g_po[BB][16][2][64][HH];   // 16 MB
__device__ __align__(16) float g_pm[BB][16][2][64];
__device__ __align__(16) float g_pl[BB][16][2][64];

#define SC2 0.12752139915237768f   // (1/sqrt(128)) * log2(e)

// ---------------------------------------------------------------------------
// PTX helpers
// ---------------------------------------------------------------------------
__device__ __forceinline__ void mma_f16(float c[4], const uint32_t a[4],
                                        uint32_t b0, uint32_t b1) {
    asm volatile(
        "mma.sync.aligned.m16n8k16.row.col.f32.f16.f16.f32 "
        "{%0,%1,%2,%3}, {%4,%5,%6,%7}, {%8,%9}, {%0,%1,%2,%3};"
        : "+f"(c[0]), "+f"(c[1]), "+f"(c[2]), "+f"(c[3])
        : "r"(a[0]), "r"(a[1]), "r"(a[2]), "r"(a[3]), "r"(b0), "r"(b1));
}

__device__ __forceinline__ void ldsm_x4(uint32_t r[4], uint32_t addr) {
    asm volatile("ldmatrix.sync.aligned.m8n8.x4.shared.b16 {%0,%1,%2,%3}, [%4];"
        : "=r"(r[0]), "=r"(r[1]), "=r"(r[2]), "=r"(r[3]) : "r"(addr));
}

__device__ __forceinline__ uint32_t smem_u32(const void* p) {
    uint32_t a;
    asm("{ .reg .u64 t; cvta.to.shared.u64 t, %1; cvt.u32.u64 %0, t; }" : "=r"(a) : "l"(p));
    return a;
}

#define CP_ASYNC16(dst, src) \
    asm volatile("cp.async.cg.shared.global [%0], [%1], 16;" :: "r"(dst), "l"(src) : "memory")
#define CP_COMMIT() asm volatile("cp.async.commit_group;" ::: "memory")
#define CP_WAIT0()  asm volatile("cp.async.wait_group 0;" ::: "memory")
#define CP_WAIT1()  asm volatile("cp.async.wait_group 1;" ::: "memory")
#define CP_WAIT2()  asm volatile("cp.async.wait_group 2;" ::: "memory")

__device__ __forceinline__ uint32_t h2u(float a, float b) {
    __half2 h = __floats2half2_rn(a, b);
    return *reinterpret_cast<uint32_t*>(&h);
}

// ===========================================================================
// Kernel 0: fp32 -> fp16 conversion, single launch for x + Wq + Wk + Wv.
// ===========================================================================
#define X8 (BB * TT * CC / 8)    // 2097152
#define W8 (HH * CC / 8)         // 16384
#define CONV_N (X8 + 3 * W8)

__global__ __launch_bounds__(256) void conv_all(
    const float4* __restrict__ x,  const float4* __restrict__ wq,
    const float4* __restrict__ wk, const float4* __restrict__ wv)
{
    int i = blockIdx.x * 256 + threadIdx.x;
    if (i >= CONV_N) return;
    const float4* src;
    __half* dst;
    int j;
    if (i < X8) {
        src = x; j = i; dst = g_xh;
    } else {
        int k = i - X8;
        int w = k / W8;
        j = k - w * W8;
        src = (w == 0) ? wq : (w == 1) ? wk : wv;
        dst = g_wh + (size_t)w * (HH * CC);
    }
    float4 a = src[2 * j];
    float4 b = src[2 * j + 1];
    uint4 o = make_uint4(h2u(a.x, a.y), h2u(a.z, a.w),
                         h2u(b.x, b.y), h2u(b.z, b.w));
    reinterpret_cast<uint4*>(dst)[j] = o;
}

// ===========================================================================
// Kernel 1: QKV projection, BM=128, BK=64, 3-stage cp.async (one sync/iter).
// Smem: 3 stages x 36864B = 110592B -> occ 2.
// mat 0 -> g_q (pre-scaled by SC2), 1 -> g_k, 2 -> g_vt (transposed).
// ===========================================================================
#define QKROW 144
#define QKB_OFF 18432
#define QKSTG 36864
#define QKV_SMEM_BYTES (3 * QKSTG)

__global__ __launch_bounds__(256, 2) void qkv_mma_kernel()
{
    extern __shared__ char smc[];
    const uint32_t sb = smem_u32(smc);
    const int mat = blockIdx.y;
    const __half* whm = g_wh + (size_t)mat * (HH * CC);

    const int tid = threadIdx.x;
    const int lid = tid & 31;
    const int wid = tid >> 5;
    const int g = lid >> 2;
    const int c = lid & 3;
    const int wm = wid & 3;
    const int wn = wid >> 2;
    const int m0 = blockIdx.x * 128;

    const uint32_t lrow = lid & 15;
    const uint32_t lhi  = lid >> 4;

    float acc[2][8][4];
    #pragma unroll
    for (int mi = 0; mi < 2; mi++)
        #pragma unroll
        for (int ni = 0; ni < 8; ni++)
            #pragma unroll
            for (int j = 0; j < 4; j++) acc[mi][ni][j] = 0.0f;

    auto cpa_stage = [&](int s, int kt) {
        const int k0 = kt * 64;
        const uint32_t base = sb + s * QKSTG;
        #pragma unroll
        for (int i = 0; i < 4; i++) {
            int idx = tid + i * 256;
            int r = idx >> 3, ch = idx & 7;
            CP_ASYNC16(base + r * QKROW + ch * 16,
                       g_xh + (size_t)(m0 + r) * CC + k0 + ch * 8);
            CP_ASYNC16(base + QKB_OFF + r * QKROW + ch * 16,
                       whm + (size_t)r * CC + k0 + ch * 8);
        }
    };

    cpa_stage(0, 0);
    CP_COMMIT();
    cpa_stage(1, 1);
    CP_COMMIT();

    for (int kt = 0; kt < 16; ++kt) {
        const int s = kt % 3;

        if (kt < 15) CP_WAIT1(); else CP_WAIT0();   // tile kt landed
        __syncthreads();                            // stage (kt+2)%3 free too

        if (kt + 2 < 16) {
            cpa_stage((kt + 2) % 3, kt + 2);
            CP_COMMIT();
        }

        const uint32_t abase = sb + s * QKSTG;
        const uint32_t bbase = abase + QKB_OFF;

        #pragma unroll
        for (int ks = 0; ks < 4; ks++) {
            const uint32_t choff = (ks * 2 + lhi) * 16;
            uint32_t a0[4], a1[4];
            ldsm_x4(a0, abase + (wm * 32 + lrow) * QKROW + choff);
            ldsm_x4(a1, abase + (wm * 32 + 16 + lrow) * QKROW + choff);
            #pragma unroll
            for (int nt2 = 0; nt2 < 4; nt2++) {
                uint32_t b4[4];
                ldsm_x4(b4, bbase + (wn * 64 + nt2 * 16 + lrow) * QKROW + choff);
                mma_f16(acc[0][2 * nt2],     a0, b4[0], b4[2]);
                mma_f16(acc[0][2 * nt2 + 1], a0, b4[1], b4[3]);
                mma_f16(acc[1][2 * nt2],     a1, b4[0], b4[2]);
                mma_f16(acc[1][2 * nt2 + 1], a1, b4[1], b4[3]);
            }
        }
    }

    if (mat < 2) {
        __half* out = (mat == 0) ? g_q : g_k;
        const float scl = (mat == 0) ? SC2 : 1.0f;   // fold softmax scale into Q
        #pragma unroll
        for (int mi = 0; mi < 2; mi++) {
            int row0 = m0 + wm * 32 + mi * 16 + g;
            int row1 = row0 + 8;
            #pragma unroll
            for (int ni = 0; ni < 8; ni++) {
                int col = wn * 64 + ni * 8 + 2 * c;
                *reinterpret_cast<uint32_t*>(&out[(size_t)row0 * HH + col]) =
                    h2u(acc[mi][ni][0] * scl, acc[mi][ni][1] * scl);
                *reinterpret_cast<uint32_t*>(&out[(size_t)row1 * HH + col]) =
                    h2u(acc[mi][ni][2] * scl, acc[mi][ni][3] * scl);
            }
        }
    } else {
        __half* vtb = g_vt + (size_t)(m0 / TT) * HH * TT;
        const int tbase = m0 % TT;
        #pragma unroll
        for (int mi = 0; mi < 2; mi++) {
            int t0 = tbase + wm * 32 + mi * 16 + g;
            int t1 = t0 + 8;
            #pragma unroll
            for (int ni = 0; ni < 8; ni++) {
                int col = wn * 64 + ni * 8 + 2 * c;
                vtb[(size_t)col * TT + t0]       = __float2half_rn(acc[mi][ni][0]);
                vtb[(size_t)(col + 1) * TT + t0] = __float2half_rn(acc[mi][ni][1]);
                vtb[(size_t)col * TT + t1]       = __float2half_rn(acc[mi][ni][2]);
                vtb[(size_t)(col + 1) * TT + t1] = __float2half_rn(acc[mi][ni][3]);
            }
        }
    }
}

// ===========================================================================
// Kernel 2: causal flash attention phase 1, split-KV (R10 body, occ 2,
// double-buffered K/VT).  Q pre-scaled -> no scale loop.
// ===========================================================================
#define QSTR  272
#define VSTR  144
#define AQb   0
#define AK0b  17408
#define AK1b  34816
#define AVT0b 52224
#define AVT1b 70656
#define APb   89088
#define ATT_SMEM_BYTES 98304

__global__ __launch_bounds__(128, 2) void attn_mma_kernel(float* __restrict__ out)
{
    extern __shared__ char smc[];
    const uint32_t sb = smem_u32(smc);

    const int b  = blockIdx.y;
    const int widx = 47 - blockIdx.x;          // heavy splits scheduled first
    int qt, ktlo, kthi, split = 0, qh = 0;
    bool partial;
    if (widx < 16) {
        qt = widx; ktlo = 0; kthi = qt; partial = false;
    } else {
        int h = widx - 16;
        qh = h >> 1;
        qt = 16 + qh;
        split = h & 1;
        int first = (qt + 2) >> 1;             // tiles in split 0
        ktlo = split ? first : 0;
        kthi = split ? qt : first - 1;
        partial = true;
    }
    const int q0 = qt * 64;

    const int tid = threadIdx.x;
    const int wid = tid >> 5;
    const int lid = tid & 31;
    const int g = lid >> 2;
    const int c = lid & 3;
    const int r0w = wid * 16;

    const __half* qg  = g_q  + (size_t)b * TT * HH;
    const __half* kg  = g_k  + (size_t)b * TT * HH;
    const __half* vtg = g_vt + (size_t)b * HH * TT;

    auto cpa64 = [&](uint32_t dstb, const __half* src) {
        #pragma unroll
        for (int i = 0; i < 8; i++) {
            int idx = tid + i * 128;
            int r = idx >> 4, ch = idx & 15;
            CP_ASYNC16(sb + dstb + r * QSTR + ch * 16,
                       src + (size_t)r * HH + ch * 8);
        }
    };
    auto cpa_vt = [&](uint32_t dstb, int kt) {
        const __half* src = vtg + kt * 64;
        #pragma unroll
        for (int i = 0; i < 8; i++) {
            int idx = tid + i * 128;
            int r = idx >> 3, ch = idx & 7;
            CP_ASYNC16(sb + dstb + r * VSTR + ch * 16,
                       src + (size_t)r * TT + ch * 8);
        }
    };

    // Prologue
    cpa64(AQb, qg + (size_t)q0 * HH);
    cpa64(AK0b, kg + (size_t)ktlo * 64 * HH);
    CP_COMMIT();
    cpa_vt(AVT0b, ktlo);
    CP_COMMIT();
    CP_WAIT1();
    __syncthreads();

    const uint32_t lrow = lid & 15;
    const uint32_t lhi  = lid >> 4;

    uint32_t qa[8][4];
    {
        const uint32_t qrb = sb + AQb + (r0w + lrow) * QSTR;
        #pragma unroll
        for (int ks = 0; ks < 8; ks++)
            ldsm_x4(qa[ks], qrb + (ks * 2 + lhi) * 16);
    }

    float o[16][4];
    #pragma unroll
    for (int nt = 0; nt < 16; nt++)
        #pragma unroll
        for (int j = 0; j < 4; j++) o[nt][j] = 0.0f;
    float m0s = -1e30f, m1s = -1e30f, l0 = 0.0f, l1 = 0.0f;

    const int grow0 = q0 + r0w + g;
    const int grow1 = grow0 + 8;

    for (int kt = ktlo; kt <= kthi; ++kt) {
        const int p = (kt - ktlo) & 1;
        const uint32_t kbase  = sb + (p ? AK1b : AK0b);
        const uint32_t vtbase = sb + (p ? AVT1b : AVT0b);

        if (kt < kthi) {
            cpa64(p ? AK0b : AK1b, kg + (size_t)(kt + 1) * 64 * HH);
            CP_COMMIT();
            cpa_vt(p ? AVT0b : AVT1b, kt + 1);
            CP_COMMIT();
            CP_WAIT2();
        } else {
            CP_WAIT0();
        }
        __syncthreads();

        // ---- S = Q K^T (Q pre-scaled: S already in log2 units) ----
        float sa[8][4];
        #pragma unroll
        for (int nt = 0; nt < 8; nt++)
            #pragma unroll
            for (int j = 0; j < 4; j++) sa[nt][j] = 0.0f;

        #pragma unroll
        for (int ks = 0; ks < 8; ks++) {
            const uint32_t choff = (ks * 2 + lhi) * 16;
            #pragma unroll
            for (int nt2 = 0; nt2 < 4; nt2++) {
                uint32_t kb[4];
                ldsm_x4(kb, kbase + (nt2 * 16 + lrow) * QSTR + choff);
                mma_f16(sa[2 * nt2],     qa[ks], kb[0], kb[2]);
                mma_f16(sa[2 * nt2 + 1], qa[ks], kb[1], kb[3]);
            }
        }

        // causal mask on the diagonal tile
        const int k0 = kt * 64;
        if (kt == qt) {
            #pragma unroll
            for (int nt = 0; nt < 8; nt++) {
                int colb = k0 + nt * 8 + 2 * c;
                if (colb     > grow0) sa[nt][0] = -1e30f;
                if (colb + 1 > grow0) sa[nt][1] = -1e30f;
                if (colb     > grow1) sa[nt][2] = -1e30f;
                if (colb + 1 > grow1) sa[nt][3] = -1e30f;
            }
        }

        // online softmax (base-2)
        float mt0 = -1e30f, mt1 = -1e30f;
        #pragma unroll
        for (int nt = 0; nt < 8; nt++) {
            mt0 = fmaxf(mt0, fmaxf(sa[nt][0], sa[nt][1]));
            mt1 = fmaxf(mt1, fmaxf(sa[nt][2], sa[nt][3]));
        }
        mt0 = fmaxf(mt0, __shfl_xor_sync(0xffffffffu, mt0, 1));
        mt0 = fmaxf(mt0, __shfl_xor_sync(0xffffffffu, mt0, 2));
        mt1 = fmaxf(mt1, __shfl_xor_sync(0xffffffffu, mt1, 1));
        mt1 = fmaxf(mt1, __shfl_xor_sync(0xffffffffu, mt1, 2));

        const float mn0 = fmaxf(m0s, mt0);
        const float mn1 = fmaxf(m1s, mt1);
        const float al0 = exp2f(m0s - mn0);
        const float al1 = exp2f(m1s - mn1);
        m0s = mn0; m1s = mn1;

        float lt0 = 0.0f, lt1 = 0.0f;
        #pragma unroll
        for (int nt = 0; nt < 8; nt++) {
            sa[nt][0] = exp2f(sa[nt][0] - mn0);
            sa[nt][1] = exp2f(sa[nt][1] - mn0);
            sa[nt][2] = exp2f(sa[nt][2] - mn1);
            sa[nt][3] = exp2f(sa[nt][3] - mn1);
            lt0 += sa[nt][0] + sa[nt][1];
            lt1 += sa[nt][2] + sa[nt][3];
        }
        lt0 += __shfl_xor_sync(0xffffffffu, lt0, 1);
        lt0 += __shfl_xor_sync(0xffffffffu, lt0, 2);
        lt1 += __shfl_xor_sync(0xffffffffu, lt1, 1);
        lt1 += __shfl_xor_sync(0xffffffffu, lt1, 2);
        l0 = l0 * al0 + lt0;
        l1 = l1 * al1 + lt1;

        #pragma unroll
        for (int nt = 0; nt < 16; nt++) {
            o[nt][0] *= al0; o[nt][1] *= al0;
            o[nt][2] *= al1; o[nt][3] *= al1;
        }

        // P -> smem fp16 (warp-private rows, padded 144B rows)
        {
            char* pr0 = smc + APb + (r0w + g) * VSTR + c * 4;
            char* pr8 = pr0 + 8 * VSTR;
            #pragma unroll
            for (int nt = 0; nt < 8; nt++) {
                *reinterpret_cast<uint32_t*>(pr0 + nt * 16) = h2u(sa[nt][0], sa[nt][1]);
                *reinterpret_cast<uint32_t*>(pr8 + nt * 16) = h2u(sa[nt][2], sa[nt][3]);
            }
        }
        __syncwarp();

        // ---- O += P V ----
        #pragma unroll
        for (int ks2 = 0; ks2 < 4; ks2++) {
            const uint32_t choff = (ks2 * 2 + lhi) * 16;
            uint32_t pa[4];
            ldsm_x4(pa, sb + APb + (r0w + lrow) * VSTR + choff);
            #pragma unroll
            for (int ntv = 0; ntv < 8; ntv++) {
                uint32_t vb[4];
                ldsm_x4(vb, vtbase + (ntv * 16 + lrow) * VSTR + choff);
                mma_f16(o[2 * ntv],     pa, vb[0], vb[2]);
                mma_f16(o[2 * ntv + 1], pa, vb[1], vb[3]);
            }
        }
        __syncthreads();
    }

    const int lr0 = r0w + g;
    const int lr1 = lr0 + 8;

    if (!partial) {
        const float inv0 = 1.0f / l0;
        const float inv1 = 1.0f / l1;
        #pragma unroll
        for (int nt = 0; nt < 16; nt++) {
            int col = nt * 8 + 2 * c;
            float2 v0 = make_float2(o[nt][0] * inv0, o[nt][1] * inv0);
            float2 v1 = make_float2(o[nt][2] * inv1, o[nt][3] * inv1);
            *reinterpret_cast<float2*>(&out[((size_t)b * TT + grow0) * HH + col]) = v0;
            *reinterpret_cast<float2*>(&out[((size_t)b * TT + grow1) * HH + col]) = v1;
        }
    } else {
        if (c == 0) {
            g_pm[b][qh][split][lr0] = m0s;
            g_pl[b][qh][split][lr0] = l0;
            g_pm[b][qh][split][lr1] = m1s;
            g_pl[b][qh][split][lr1] = l1;
        }
        #pragma unroll
        for (int nt = 0; nt < 16; nt++) {
            int col = nt * 8 + 2 * c;
            *reinterpret_cast<float2*>(&g_po[b][qh][split][lr0][col]) =
                make_float2(o[nt][0], o[nt][1]);
            *reinterpret_cast<float2*>(&g_po[b][qh][split][lr1][col]) =
                make_float2(o[nt][2], o[nt][3]);
        }
    }
}

// ===========================================================================
// Kernel 3: combine split-KV partials for heavy q-tiles.  grid (16, 8).
// ===========================================================================
__global__ __launch_bounds__(256) void attn_combine(float* __restrict__ out)
{
    const int b = blockIdx.y;
    const int qh = blockIdx.x;
    const int qt = 16 + qh;
    const int t = threadIdx.x;
    const int colb = (t & 31) * 4;
    const int rbase = t >> 5;

    #pragma unroll
    for (int pass = 0; pass < 8; pass++) {
        const int row = pass * 8 + rbase;
        const float m0 = g_pm[b][qh][0][row];
        const float m1 = g_pm[b][qh][1][row];
        const float m = fmaxf(m0, m1);
        const float a0 = exp2f(m0 - m);
        const float a1 = exp2f(m1 - m);
        const float invl = 1.0f / (g_pl[b][qh][0][row] * a0 + g_pl[b][qh][1][row] * a1);
        const float4 O0 = *reinterpret_cast<const float4*>(&g_po[b][qh][0][row][colb]);
        const float4 O1 = *reinterpret_cast<const float4*>(&g_po[b][qh][1][row][colb]);
        float4 r;
        r.x = (O0.x * a0 + O1.x * a1) * invl;
        r.y = (O0.y * a0 + O1.y * a1) * invl;
        r.z = (O0.z * a0 + O1.z * a1) * invl;
        r.w = (O0.w * a0 + O1.w * a1) * invl;
        *reinterpret_cast<float4*>(
            &out[((size_t)b * TT + qt * 64 + row) * HH + colb]) = r;
    }
}

// ---------------------------------------------------------------------------
extern "C" void kernel_launch(void* const* d_in, const int* in_sizes, int n_in,
                              void* d_out, int out_size)
{
    const float* x  = (const float*)d_in[0];
    const float* Wq = (const float*)d_in[1];
    const float* Wk = (const float*)d_in[2];
    const float* Wv = (const float*)d_in[3];
    float* out = (float*)d_out;

    cudaFuncSetAttribute(qkv_mma_kernel, cudaFuncAttributeMaxDynamicSharedMemorySize,
                         QKV_SMEM_BYTES);
    cudaFuncSetAttribute(attn_mma_kernel, cudaFuncAttributeMaxDynamicSharedMemorySize,
                         ATT_SMEM_BYTES);

    conv_all<<<(CONV_N + 255) / 256, 256>>>((const float4*)x, (const float4*)Wq,
                                            (const float4*)Wk, (const float4*)Wv);

    dim3 g1((BB * TT) / 128, 3);
    qkv_mma_kernel<<<g1, 256, QKV_SMEM_BYTES>>>();

    dim3 g2(48, BB);
    attn_mma_kernel<<<g2, 128, ATT_SMEM_BYTES>>>(out);

    dim3 g3(16, BB);
    attn_combine<<<g3, 256>>>(out);
}

// round 17
// speedup vs baseline: 1.1271x; 1.0135x over previous
#include <cuda_runtime.h>
#include <cuda_fp16.h>
#include <math.h>
#include <stdint.h>

#define BB 8
#define TT 2048
#define CC 1024
#define HH 128

__device__ __align__(16) __half g_q[BB * TT * HH];    // pre-scaled by sc*log2e
__device__ __align__(16) __half g_k[BB * TT * HH];
__device__ __align__(16) __half g_vt[BB * HH * TT];   // V transposed: [b][h][t]
__device__ __align__(16) __half g_xh[BB * TT * CC];   // x in fp16
__device__ __align__(16) __half g_wh[3 * HH * CC];    // Wq/Wk/Wv in fp16

// Split-KV partials for heavy q-tiles (qt 16..31): O unnormalized + m,l
__device__ __align__(16) float g_po[BB][16][2][64][HH];   // 16 MB
__device__ __align__(16) float g_pm[BB][16][2][64];
__device__ __align__(16) float g_pl[BB][16][2][64];

#define SC2 0.12752139915237768f   // (1/sqrt(128)) * log2(e)

// ---------------------------------------------------------------------------
// PTX helpers
// ---------------------------------------------------------------------------
__device__ __forceinline__ void mma_f16(float c[4], const uint32_t a[4],
                                        uint32_t b0, uint32_t b1) {
    asm volatile(
        "mma.sync.aligned.m16n8k16.row.col.f32.f16.f16.f32 "
        "{%0,%1,%2,%3}, {%4,%5,%6,%7}, {%8,%9}, {%0,%1,%2,%3};"
        : "+f"(c[0]), "+f"(c[1]), "+f"(c[2]), "+f"(c[3])
        : "r"(a[0]), "r"(a[1]), "r"(a[2]), "r"(a[3]), "r"(b0), "r"(b1));
}

__device__ __forceinline__ void ldsm_x4(uint32_t r[4], uint32_t addr) {
    asm volatile("ldmatrix.sync.aligned.m8n8.x4.shared.b16 {%0,%1,%2,%3}, [%4];"
        : "=r"(r[0]), "=r"(r[1]), "=r"(r[2]), "=r"(r[3]) : "r"(addr));
}

__device__ __forceinline__ uint32_t smem_u32(const void* p) {
    uint32_t a;
    asm("{ .reg .u64 t; cvta.to.shared.u64 t, %1; cvt.u32.u64 %0, t; }" : "=r"(a) : "l"(p));
    return a;
}

#define CP_ASYNC16(dst, src) \
    asm volatile("cp.async.cg.shared.global [%0], [%1], 16;" :: "r"(dst), "l"(src) : "memory")
#define CP_COMMIT() asm volatile("cp.async.commit_group;" ::: "memory")
#define CP_WAIT0()  asm volatile("cp.async.wait_group 0;" ::: "memory")
#define CP_WAIT1()  asm volatile("cp.async.wait_group 1;" ::: "memory")
#define CP_WAIT2()  asm volatile("cp.async.wait_group 2;" ::: "memory")

__device__ __forceinline__ uint32_t h2u(float a, float b) {
    __half2 h = __floats2half2_rn(a, b);
    return *reinterpret_cast<uint32_t*>(&h);
}

// ===========================================================================
// Kernel 0: fp32 -> fp16 conversion, single launch for x + Wq + Wk + Wv.
// ===========================================================================
#define X8 (BB * TT * CC / 8)    // 2097152
#define W8 (HH * CC / 8)         // 16384
#define CONV_N (X8 + 3 * W8)

__global__ __launch_bounds__(256) void conv_all(
    const float4* __restrict__ x,  const float4* __restrict__ wq,
    const float4* __restrict__ wk, const float4* __restrict__ wv)
{
    int i = blockIdx.x * 256 + threadIdx.x;
    if (i >= CONV_N) return;
    const float4* src;
    __half* dst;
    int j;
    if (i < X8) {
        src = x; j = i; dst = g_xh;
    } else {
        int k = i - X8;
        int w = k / W8;
        j = k - w * W8;
        src = (w == 0) ? wq : (w == 1) ? wk : wv;
        dst = g_wh + (size_t)w * (HH * CC);
    }
    float4 a = src[2 * j];
    float4 b = src[2 * j + 1];
    uint4 o = make_uint4(h2u(a.x, a.y), h2u(a.z, a.w),
                         h2u(b.x, b.y), h2u(b.z, b.w));
    reinterpret_cast<uint4*>(dst)[j] = o;
}

// ===========================================================================
// Kernel 1: QKV projection, BM=128, BK=64, 3-stage cp.async (one sync/iter).
// Smem: 3 stages x 36864B = 110592B -> occ 2.
// mat 0 -> g_q (pre-scaled by SC2), 1 -> g_k, 2 -> g_vt (transposed).
// ===========================================================================
#define QKROW 144
#define QKB_OFF 18432
#define QKSTG 36864
#define QKV_SMEM_BYTES (3 * QKSTG)

__global__ __launch_bounds__(256, 2) void qkv_mma_kernel()
{
    extern __shared__ char smc[];
    const uint32_t sb = smem_u32(smc);
    const int mat = blockIdx.y;
    const __half* whm = g_wh + (size_t)mat * (HH * CC);

    const int tid = threadIdx.x;
    const int lid = tid & 31;
    const int wid = tid >> 5;
    const int g = lid >> 2;
    const int c = lid & 3;
    const int wm = wid & 3;
    const int wn = wid >> 2;
    const int m0 = blockIdx.x * 128;

    const uint32_t lrow = lid & 15;
    const uint32_t lhi  = lid >> 4;

    float acc[2][8][4];
    #pragma unroll
    for (int mi = 0; mi < 2; mi++)
        #pragma unroll
        for (int ni = 0; ni < 8; ni++)
            #pragma unroll
            for (int j = 0; j < 4; j++) acc[mi][ni][j] = 0.0f;

    auto cpa_stage = [&](int s, int kt) {
        const int k0 = kt * 64;
        const uint32_t base = sb + s * QKSTG;
        #pragma unroll
        for (int i = 0; i < 4; i++) {
            int idx = tid + i * 256;
            int r = idx >> 3, ch = idx & 7;
            CP_ASYNC16(base + r * QKROW + ch * 16,
                       g_xh + (size_t)(m0 + r) * CC + k0 + ch * 8);
            CP_ASYNC16(base + QKB_OFF + r * QKROW + ch * 16,
                       whm + (size_t)r * CC + k0 + ch * 8);
        }
    };

    cpa_stage(0, 0);
    CP_COMMIT();
    cpa_stage(1, 1);
    CP_COMMIT();

    for (int kt = 0; kt < 16; ++kt) {
        const int s = kt % 3;

        if (kt < 15) CP_WAIT1(); else CP_WAIT0();   // tile kt landed
        __syncthreads();                            // stage (kt+2)%3 free too

        if (kt + 2 < 16) {
            cpa_stage((kt + 2) % 3, kt + 2);
            CP_COMMIT();
        }

        const uint32_t abase = sb + s * QKSTG;
        const uint32_t bbase = abase + QKB_OFF;

        #pragma unroll
        for (int ks = 0; ks < 4; ks++) {
            const uint32_t choff = (ks * 2 + lhi) * 16;
            uint32_t a0[4], a1[4];
            ldsm_x4(a0, abase + (wm * 32 + lrow) * QKROW + choff);
            ldsm_x4(a1, abase + (wm * 32 + 16 + lrow) * QKROW + choff);
            #pragma unroll
            for (int nt2 = 0; nt2 < 4; nt2++) {
                uint32_t b4[4];
                ldsm_x4(b4, bbase + (wn * 64 + nt2 * 16 + lrow) * QKROW + choff);
                mma_f16(acc[0][2 * nt2],     a0, b4[0], b4[2]);
                mma_f16(acc[0][2 * nt2 + 1], a0, b4[1], b4[3]);
                mma_f16(acc[1][2 * nt2],     a1, b4[0], b4[2]);
                mma_f16(acc[1][2 * nt2 + 1], a1, b4[1], b4[3]);
            }
        }
    }

    if (mat < 2) {
        __half* out = (mat == 0) ? g_q : g_k;
        const float scl = (mat == 0) ? SC2 : 1.0f;   // fold softmax scale into Q
        #pragma unroll
        for (int mi = 0; mi < 2; mi++) {
            int row0 = m0 + wm * 32 + mi * 16 + g;
            int row1 = row0 + 8;
            #pragma unroll
            for (int ni = 0; ni < 8; ni++) {
                int col = wn * 64 + ni * 8 + 2 * c;
                *reinterpret_cast<uint32_t*>(&out[(size_t)row0 * HH + col]) =
                    h2u(acc[mi][ni][0] * scl, acc[mi][ni][1] * scl);
                *reinterpret_cast<uint32_t*>(&out[(size_t)row1 * HH + col]) =
                    h2u(acc[mi][ni][2] * scl, acc[mi][ni][3] * scl);
            }
        }
    } else {
        __half* vtb = g_vt + (size_t)(m0 / TT) * HH * TT;
        const int tbase = m0 % TT;
        #pragma unroll
        for (int mi = 0; mi < 2; mi++) {
            int t0 = tbase + wm * 32 + mi * 16 + g;
            int t1 = t0 + 8;
            #pragma unroll
            for (int ni = 0; ni < 8; ni++) {
                int col = wn * 64 + ni * 8 + 2 * c;
                vtb[(size_t)col * TT + t0]       = __float2half_rn(acc[mi][ni][0]);
                vtb[(size_t)(col + 1) * TT + t0] = __float2half_rn(acc[mi][ni][1]);
                vtb[(size_t)col * TT + t1]       = __float2half_rn(acc[mi][ni][2]);
                vtb[(size_t)(col + 1) * TT + t1] = __float2half_rn(acc[mi][ni][3]);
            }
        }
    }
}

// ===========================================================================
// Kernel 2: causal flash attention phase 1, split-KV (R16 body, unchanged).
// ===========================================================================
#define QSTR  272
#define VSTR  144
#define AQb   0
#define AK0b  17408
#define AK1b  34816
#define AVT0b 52224
#define AVT1b 70656
#define APb   89088
#define ATT_SMEM_BYTES 98304

__global__ __launch_bounds__(128, 2) void attn_mma_kernel(float* __restrict__ out)
{
    extern __shared__ char smc[];
    const uint32_t sb = smem_u32(smc);

    const int b  = blockIdx.y;
    const int widx = 47 - blockIdx.x;          // heavy splits scheduled first
    int qt, ktlo, kthi, split = 0, qh = 0;
    bool partial;
    if (widx < 16) {
        qt = widx; ktlo = 0; kthi = qt; partial = false;
    } else {
        int h = widx - 16;
        qh = h >> 1;
        qt = 16 + qh;
        split = h & 1;
        int first = (qt + 2) >> 1;             // tiles in split 0
        ktlo = split ? first : 0;
        kthi = split ? qt : first - 1;
        partial = true;
    }
    const int q0 = qt * 64;

    const int tid = threadIdx.x;
    const int wid = tid >> 5;
    const int lid = tid & 31;
    const int g = lid >> 2;
    const int c = lid & 3;
    const int r0w = wid * 16;

    const __half* qg  = g_q  + (size_t)b * TT * HH;
    const __half* kg  = g_k  + (size_t)b * TT * HH;
    const __half* vtg = g_vt + (size_t)b * HH * TT;

    auto cpa64 = [&](uint32_t dstb, const __half* src) {
        #pragma unroll
        for (int i = 0; i < 8; i++) {
            int idx = tid + i * 128;
            int r = idx >> 4, ch = idx & 15;
            CP_ASYNC16(sb + dstb + r * QSTR + ch * 16,
                       src + (size_t)r * HH + ch * 8);
        }
    };
    auto cpa_vt = [&](uint32_t dstb, int kt) {
        const __half* src = vtg + kt * 64;
        #pragma unroll
        for (int i = 0; i < 8; i++) {
            int idx = tid + i * 128;
            int r = idx >> 3, ch = idx & 7;
            CP_ASYNC16(sb + dstb + r * VSTR + ch * 16,
                       src + (size_t)r * TT + ch * 8);
        }
    };

    // Prologue
    cpa64(AQb, qg + (size_t)q0 * HH);
    cpa64(AK0b, kg + (size_t)ktlo * 64 * HH);
    CP_COMMIT();
    cpa_vt(AVT0b, ktlo);
    CP_COMMIT();
    CP_WAIT1();
    __syncthreads();

    const uint32_t lrow = lid & 15;
    const uint32_t lhi  = lid >> 4;

    uint32_t qa[8][4];
    {
        const uint32_t qrb = sb + AQb + (r0w + lrow) * QSTR;
        #pragma unroll
        for (int ks = 0; ks < 8; ks++)
            ldsm_x4(qa[ks], qrb + (ks * 2 + lhi) * 16);
    }

    float o[16][4];
    #pragma unroll
    for (int nt = 0; nt < 16; nt++)
        #pragma unroll
        for (int j = 0; j < 4; j++) o[nt][j] = 0.0f;
    float m0s = -1e30f, m1s = -1e30f, l0 = 0.0f, l1 = 0.0f;

    const int grow0 = q0 + r0w + g;
    const int grow1 = grow0 + 8;

    for (int kt = ktlo; kt <= kthi; ++kt) {
        const int p = (kt - ktlo) & 1;
        const uint32_t kbase  = sb + (p ? AK1b : AK0b);
        const uint32_t vtbase = sb + (p ? AVT1b : AVT0b);

        if (kt < kthi) {
            cpa64(p ? AK0b : AK1b, kg + (size_t)(kt + 1) * 64 * HH);
            CP_COMMIT();
            cpa_vt(p ? AVT0b : AVT1b, kt + 1);
            CP_COMMIT();
            CP_WAIT2();
        } else {
            CP_WAIT0();
        }
        __syncthreads();

        // ---- S = Q K^T (Q pre-scaled: S already in log2 units) ----
        float sa[8][4];
        #pragma unroll
        for (int nt = 0; nt < 8; nt++)
            #pragma unroll
            for (int j = 0; j < 4; j++) sa[nt][j] = 0.0f;

        #pragma unroll
        for (int ks = 0; ks < 8; ks++) {
            const uint32_t choff = (ks * 2 + lhi) * 16;
            #pragma unroll
            for (int nt2 = 0; nt2 < 4; nt2++) {
                uint32_t kb[4];
                ldsm_x4(kb, kbase + (nt2 * 16 + lrow) * QSTR + choff);
                mma_f16(sa[2 * nt2],     qa[ks], kb[0], kb[2]);
                mma_f16(sa[2 * nt2 + 1], qa[ks], kb[1], kb[3]);
            }
        }

        // causal mask on the diagonal tile
        const int k0 = kt * 64;
        if (kt == qt) {
            #pragma unroll
            for (int nt = 0; nt < 8; nt++) {
                int colb = k0 + nt * 8 + 2 * c;
                if (colb     > grow0) sa[nt][0] = -1e30f;
                if (colb + 1 > grow0) sa[nt][1] = -1e30f;
                if (colb     > grow1) sa[nt][2] = -1e30f;
                if (colb + 1 > grow1) sa[nt][3] = -1e30f;
            }
        }

        // online softmax (base-2)
        float mt0 = -1e30f, mt1 = -1e30f;
        #pragma unroll
        for (int nt = 0; nt < 8; nt++) {
            mt0 = fmaxf(mt0, fmaxf(sa[nt][0], sa[nt][1]));
            mt1 = fmaxf(mt1, fmaxf(sa[nt][2], sa[nt][3]));
        }
        mt0 = fmaxf(mt0, __shfl_xor_sync(0xffffffffu, mt0, 1));
        mt0 = fmaxf(mt0, __shfl_xor_sync(0xffffffffu, mt0, 2));
        mt1 = fmaxf(mt1, __shfl_xor_sync(0xffffffffu, mt1, 1));
        mt1 = fmaxf(mt1, __shfl_xor_sync(0xffffffffu, mt1, 2));

        const float mn0 = fmaxf(m0s, mt0);
        const float mn1 = fmaxf(m1s, mt1);
        const float al0 = exp2f(m0s - mn0);
        const float al1 = exp2f(m1s - mn1);
        m0s = mn0; m1s = mn1;

        float lt0 = 0.0f, lt1 = 0.0f;
        #pragma unroll
        for (int nt = 0; nt < 8; nt++) {
            sa[nt][0] = exp2f(sa[nt][0] - mn0);
            sa[nt][1] = exp2f(sa[nt][1] - mn0);
            sa[nt][2] = exp2f(sa[nt][2] - mn1);
            sa[nt][3] = exp2f(sa[nt][3] - mn1);
            lt0 += sa[nt][0] + sa[nt][1];
            lt1 += sa[nt][2] + sa[nt][3];
        }
        lt0 += __shfl_xor_sync(0xffffffffu, lt0, 1);
        lt0 += __shfl_xor_sync(0xffffffffu, lt0, 2);
        lt1 += __shfl_xor_sync(0xffffffffu, lt1, 1);
        lt1 += __shfl_xor_sync(0xffffffffu, lt1, 2);
        l0 = l0 * al0 + lt0;
        l1 = l1 * al1 + lt1;

        #pragma unroll
        for (int nt = 0; nt < 16; nt++) {
            o[nt][0] *= al0; o[nt][1] *= al0;
            o[nt][2] *= al1; o[nt][3] *= al1;
        }

        // P -> smem fp16 (warp-private rows, padded 144B rows)
        {
            char* pr0 = smc + APb + (r0w + g) * VSTR + c * 4;
            char* pr8 = pr0 + 8 * VSTR;
            #pragma unroll
            for (int nt = 0; nt < 8; nt++) {
                *reinterpret_cast<uint32_t*>(pr0 + nt * 16) = h2u(sa[nt][0], sa[nt][1]);
                *reinterpret_cast<uint32_t*>(pr8 + nt * 16) = h2u(sa[nt][2], sa[nt][3]);
            }
        }
        __syncwarp();

        // ---- O += P V ----
        #pragma unroll
        for (int ks2 = 0; ks2 < 4; ks2++) {
            const uint32_t choff = (ks2 * 2 + lhi) * 16;
            uint32_t pa[4];
            ldsm_x4(pa, sb + APb + (r0w + lrow) * VSTR + choff);
            #pragma unroll
            for (int ntv = 0; ntv < 8; ntv++) {
                uint32_t vb[4];
                ldsm_x4(vb, vtbase + (ntv * 16 + lrow) * VSTR + choff);
                mma_f16(o[2 * ntv],     pa, vb[0], vb[2]);
                mma_f16(o[2 * ntv + 1], pa, vb[1], vb[3]);
            }
        }
        __syncthreads();
    }

    const int lr0 = r0w + g;
    const int lr1 = lr0 + 8;

    if (!partial) {
        const float inv0 = 1.0f / l0;
        const float inv1 = 1.0f / l1;
        #pragma unroll
        for (int nt = 0; nt < 16; nt++) {
            int col = nt * 8 + 2 * c;
            float2 v0 = make_float2(o[nt][0] * inv0, o[nt][1] * inv0);
            float2 v1 = make_float2(o[nt][2] * inv1, o[nt][3] * inv1);
            *reinterpret_cast<float2*>(&out[((size_t)b * TT + grow0) * HH + col]) = v0;
            *reinterpret_cast<float2*>(&out[((size_t)b * TT + grow1) * HH + col]) = v1;
        }
    } else {
        if (c == 0) {
            g_pm[b][qh][split][lr0] = m0s;
            g_pl[b][qh][split][lr0] = l0;
            g_pm[b][qh][split][lr1] = m1s;
            g_pl[b][qh][split][lr1] = l1;
        }
        #pragma unroll
        for (int nt = 0; nt < 16; nt++) {
            int col = nt * 8 + 2 * c;
            *reinterpret_cast<float2*>(&g_po[b][qh][split][lr0][col]) =
                make_float2(o[nt][0], o[nt][1]);
            *reinterpret_cast<float2*>(&g_po[b][qh][split][lr1][col]) =
                make_float2(o[nt][2], o[nt][3]);
        }
    }
}

// ===========================================================================
// Kernel 3: combine split-KV partials — fully parallel, 1 float4 per thread.
// Total work: 8 b x 16 qh x 64 rows x 32 float4 = 262,144 threads.
// 32 consecutive threads share one row's (m,l) -> L1 broadcast.
// ===========================================================================
#define COMB_N (BB * 16 * 64 * 32)

__global__ __launch_bounds__(256) void attn_combine(float* __restrict__ out)
{
    const int idx = blockIdx.x * 256 + threadIdx.x;
    const int colb = (idx & 31) * 4;
    const int row  = (idx >> 5) & 63;
    const int qh   = (idx >> 11) & 15;
    const int b    = idx >> 15;

    const float m0 = g_pm[b][qh][0][row];
    const float m1 = g_pm[b][qh][1][row];
    const float m = fmaxf(m0, m1);
    const float a0 = exp2f(m0 - m);
    const float a1 = exp2f(m1 - m);
    const float invl = 1.0f / (g_pl[b][qh][0][row] * a0 + g_pl[b][qh][1][row] * a1);
    const float4 O0 = *reinterpret_cast<const float4*>(&g_po[b][qh][0][row][colb]);
    const float4 O1 = *reinterpret_cast<const float4*>(&g_po[b][qh][1][row][colb]);
    float4 r;
    r.x = (O0.x * a0 + O1.x * a1) * invl;
    r.y = (O0.y * a0 + O1.y * a1) * invl;
    r.z = (O0.z * a0 + O1.z * a1) * invl;
    r.w = (O0.w * a0 + O1.w * a1) * invl;
    *reinterpret_cast<float4*>(
        &out[((size_t)b * TT + (16 + qh) * 64 + row) * HH + colb]) = r;
}

// ---------------------------------------------------------------------------
extern "C" void kernel_launch(void* const* d_in, const int* in_sizes, int n_in,
                              void* d_out, int out_size)
{
    const float* x  = (const float*)d_in[0];
    const float* Wq = (const float*)d_in[1];
    const float* Wk = (const float*)d_in[2];
    const float* Wv = (const float*)d_in[3];
    float* out = (float*)d_out;

    cudaFuncSetAttribute(qkv_mma_kernel, cudaFuncAttributeMaxDynamicSharedMemorySize,
                         QKV_SMEM_BYTES);
    cudaFuncSetAttribute(attn_mma_kernel, cudaFuncAttributeMaxDynamicSharedMemorySize,
                         ATT_SMEM_BYTES);

    conv_all<<<(CONV_N + 255) / 256, 256>>>((const float4*)x, (const float4*)Wq,
                                            (const float4*)Wk, (const float4*)Wv);

    dim3 g1((BB * TT) / 128, 3);
    qkv_mma_kernel<<<g1, 256, QKV_SMEM_BYTES>>>();

    dim3 g2(48, BB);
    attn_mma_kernel<<<g2, 128, ATT_SMEM_BYTES>>>(out);

    attn_combine<<<COMB_N / 256, 256>>>(out);
}